// round 3
// baseline (speedup 1.0000x reference)
#include <cuda_runtime.h>

// MI over 8192x8192 fp32 contingency table, single-pass decomposition:
//   MI = sum_{c>0} c*log2(c) - sum_i mx_i*log2(mx_i) - sum_j my_j*log2(my_j)
// Round 3: 512-thread blocks (128-reg budget) so 16 LDG.128 can be truly
// front-batched per thread; __ldcs streaming loads; 4-way clogc accumulators;
// main pass split into two half-matrix kernels (also shifts ncu capture index).

#define NROWS 8192
#define MCOLS 8192
#define HALF  4096
#define NTHREADS 512
#define NBLOCKS 148

__device__ float  g_rowsum[NROWS];
__device__ float  g_colsum[MCOLS];
__device__ double g_clogc;

__global__ void mi_zero_kernel() {
    int t = blockIdx.x * blockDim.x + threadIdx.x;
    int stride = gridDim.x * blockDim.x;
    for (int i = t; i < NROWS; i += stride) g_rowsum[i] = 0.0f;
    for (int i = t; i < MCOLS; i += stride) g_colsum[i] = 0.0f;
    if (t == 0) g_clogc = 0.0;
}

// c*log2(c) masked at c>0, branchless, exact at c==0 (0 * finite = 0).
__device__ __forceinline__ void clog2c(float v, float& acc) {
    acc = __fmaf_rn(v, __log2f(fmaxf(v, 1e-30f)), acc);
}
__device__ __forceinline__ void clog4(const float4& v, float& acc) {
    clog2c(v.x, acc); clog2c(v.y, acc); clog2c(v.z, acc); clog2c(v.w, acc);
}
__device__ __forceinline__ float sum4(const float4& v) {
    return (v.x + v.y) + (v.z + v.w);
}
__device__ __forceinline__ void acc4(float4& a, const float4& p, const float4& q,
                                     const float4& r, const float4& s) {
    a.x += (p.x + q.x) + (r.x + s.x);
    a.y += (p.y + q.y) + (r.y + s.y);
    a.z += (p.z + q.z) + (r.z + s.z);
    a.w += (p.w + q.w) + (r.w + s.w);
}

__global__ __launch_bounds__(NTHREADS, 1)
void mi_main_kernel(const float* __restrict__ C, int row_base) {
    const int t = threadIdx.x;
    const int b = blockIdx.x;

    // Thread-fixed column ownership: 16 columns = float4 slots
    // {t, t+512, t+1024, t+1536}.
    float4 ca0 = {0,0,0,0}, ca1 = {0,0,0,0}, ca2 = {0,0,0,0}, ca3 = {0,0,0,0};
    float cl0 = 0.f, cl1 = 0.f, cl2 = 0.f, cl3 = 0.f;

    const int cnt = (HALF - 1 - b) / NBLOCKS + 1;  // rows owned by this block

    int k = 0;
    for (; k + 4 <= cnt; k += 4) {
        const int r0 = row_base + b + (k + 0) * NBLOCKS;
        const int r1 = row_base + b + (k + 1) * NBLOCKS;
        const int r2 = row_base + b + (k + 2) * NBLOCKS;
        const int r3 = row_base + b + (k + 3) * NBLOCKS;
        const float4* p0 = reinterpret_cast<const float4*>(C + (size_t)r0 * MCOLS);
        const float4* p1 = reinterpret_cast<const float4*>(C + (size_t)r1 * MCOLS);
        const float4* p2 = reinterpret_cast<const float4*>(C + (size_t)r2 * MCOLS);
        const float4* p3 = reinterpret_cast<const float4*>(C + (size_t)r3 * MCOLS);

        // 16 independent streaming loads in flight per thread (64 data regs).
        float4 a0 = __ldcs(p0 + t), a1 = __ldcs(p0 + t + 512),
               a2 = __ldcs(p0 + t + 1024), a3 = __ldcs(p0 + t + 1536);
        float4 b0 = __ldcs(p1 + t), b1 = __ldcs(p1 + t + 512),
               b2 = __ldcs(p1 + t + 1024), b3 = __ldcs(p1 + t + 1536);
        float4 c0 = __ldcs(p2 + t), c1 = __ldcs(p2 + t + 512),
               c2 = __ldcs(p2 + t + 1024), c3 = __ldcs(p2 + t + 1536);
        float4 d0 = __ldcs(p3 + t), d1 = __ldcs(p3 + t + 512),
               d2 = __ldcs(p3 + t + 1024), d3 = __ldcs(p3 + t + 1536);

        // Row sums (4 independent values per thread, 16 elems each).
        float rs0 = (sum4(a0) + sum4(a1)) + (sum4(a2) + sum4(a3));
        float rs1 = (sum4(b0) + sum4(b1)) + (sum4(b2) + sum4(b3));
        float rs2 = (sum4(c0) + sum4(c1)) + (sum4(c2) + sum4(c3));
        float rs3 = (sum4(d0) + sum4(d1)) + (sum4(d2) + sum4(d3));

        // Column accumulators (register-resident; tree over the 4 rows).
        acc4(ca0, a0, b0, c0, d0);
        acc4(ca1, a1, b1, c1, d1);
        acc4(ca2, a2, b2, c2, d2);
        acc4(ca3, a3, b3, c3, d3);

        // 4 independent c*log2(c) accumulator chains.
        clog4(a0, cl0); clog4(b0, cl0); clog4(c0, cl0); clog4(d0, cl0);
        clog4(a1, cl1); clog4(b1, cl1); clog4(c1, cl1); clog4(d1, cl1);
        clog4(a2, cl2); clog4(b2, cl2); clog4(c2, cl2); clog4(d2, cl2);
        clog4(a3, cl3); clog4(b3, cl3); clog4(c3, cl3); clog4(d3, cl3);

        // 4 interleaved shuffle-reduction chains; 1 red.global per warp per row.
        #pragma unroll
        for (int off = 16; off > 0; off >>= 1) {
            rs0 += __shfl_down_sync(0xffffffffu, rs0, off);
            rs1 += __shfl_down_sync(0xffffffffu, rs1, off);
            rs2 += __shfl_down_sync(0xffffffffu, rs2, off);
            rs3 += __shfl_down_sync(0xffffffffu, rs3, off);
        }
        if ((t & 31) == 0) {
            atomicAdd(&g_rowsum[r0], rs0);
            atomicAdd(&g_rowsum[r1], rs1);
            atomicAdd(&g_rowsum[r2], rs2);
            atomicAdd(&g_rowsum[r3], rs3);
        }
    }

    // Tail rows (0..3).
    for (; k < cnt; ++k) {
        const int r = row_base + b + k * NBLOCKS;
        const float4* p = reinterpret_cast<const float4*>(C + (size_t)r * MCOLS);
        float4 v0 = __ldcs(p + t), v1 = __ldcs(p + t + 512),
               v2 = __ldcs(p + t + 1024), v3 = __ldcs(p + t + 1536);

        float rs = (sum4(v0) + sum4(v1)) + (sum4(v2) + sum4(v3));

        ca0.x += v0.x; ca0.y += v0.y; ca0.z += v0.z; ca0.w += v0.w;
        ca1.x += v1.x; ca1.y += v1.y; ca1.z += v1.z; ca1.w += v1.w;
        ca2.x += v2.x; ca2.y += v2.y; ca2.z += v2.z; ca2.w += v2.w;
        ca3.x += v3.x; ca3.y += v3.y; ca3.z += v3.z; ca3.w += v3.w;

        clog4(v0, cl0); clog4(v1, cl1); clog4(v2, cl2); clog4(v3, cl3);

        #pragma unroll
        for (int off = 16; off > 0; off >>= 1)
            rs += __shfl_down_sync(0xffffffffu, rs, off);
        if ((t & 31) == 0)
            atomicAdd(&g_rowsum[r], rs);
    }

    // Flush column accumulators: 148 atomics per column address per half.
    int c0i = 4 * t;
    atomicAdd(&g_colsum[c0i + 0], ca0.x);
    atomicAdd(&g_colsum[c0i + 1], ca0.y);
    atomicAdd(&g_colsum[c0i + 2], ca0.z);
    atomicAdd(&g_colsum[c0i + 3], ca0.w);
    int c1i = 2048 + 4 * t;
    atomicAdd(&g_colsum[c1i + 0], ca1.x);
    atomicAdd(&g_colsum[c1i + 1], ca1.y);
    atomicAdd(&g_colsum[c1i + 2], ca1.z);
    atomicAdd(&g_colsum[c1i + 3], ca1.w);
    int c2i = 4096 + 4 * t;
    atomicAdd(&g_colsum[c2i + 0], ca2.x);
    atomicAdd(&g_colsum[c2i + 1], ca2.y);
    atomicAdd(&g_colsum[c2i + 2], ca2.z);
    atomicAdd(&g_colsum[c2i + 3], ca2.w);
    int c3i = 6144 + 4 * t;
    atomicAdd(&g_colsum[c3i + 0], ca3.x);
    atomicAdd(&g_colsum[c3i + 1], ca3.y);
    atomicAdd(&g_colsum[c3i + 2], ca3.z);
    atomicAdd(&g_colsum[c3i + 3], ca3.w);

    // Cross-thread clogc reduction in double; one double atomic per warp.
    double d = (double)((cl0 + cl1) + (cl2 + cl3));
    #pragma unroll
    for (int off = 16; off > 0; off >>= 1)
        d += __shfl_down_sync(0xffffffffu, d, off);
    if ((t & 31) == 0)
        atomicAdd(&g_clogc, d);
}

__global__ __launch_bounds__(NTHREADS)
void mi_final_kernel(float* __restrict__ out) {
    const int t = threadIdx.x;
    double local = 0.0;
    for (int i = t; i < NROWS; i += NTHREADS) {
        double mx = (double)g_rowsum[i];
        if (mx > 0.0) local += mx * log2(mx);
    }
    for (int j = t; j < MCOLS; j += NTHREADS) {
        double my = (double)g_colsum[j];
        if (my > 0.0) local += my * log2(my);
    }

    __shared__ double sh[NTHREADS / 32];
    #pragma unroll
    for (int off = 16; off > 0; off >>= 1)
        local += __shfl_down_sync(0xffffffffu, local, off);
    if ((t & 31) == 0) sh[t >> 5] = local;
    __syncthreads();
    if (t < 32) {
        double v = (t < (NTHREADS / 32)) ? sh[t] : 0.0;
        #pragma unroll
        for (int off = 16; off > 0; off >>= 1)
            v += __shfl_down_sync(0xffffffffu, v, off);
        if (t == 0)
            out[0] = (float)(g_clogc - v);
    }
}

extern "C" void kernel_launch(void* const* d_in, const int* in_sizes, int n_in,
                              void* d_out, int out_size) {
    const float* C = (const float*)d_in[0];
    float* out = (float*)d_out;

    mi_zero_kernel<<<16, 1024>>>();
    mi_main_kernel<<<NBLOCKS, NTHREADS>>>(C, 0);
    mi_main_kernel<<<NBLOCKS, NTHREADS>>>(C, HALF);
    mi_final_kernel<<<1, NTHREADS>>>(out);
}

// round 4
// speedup vs baseline: 1.4194x; 1.4194x over previous
#include <cuda_runtime.h>

// MI over 8192x8192 fp32 contingency table, single-pass decomposition:
//   MI = sum_{c>0} c*log2(c) - sum_i mx_i*log2(mx_i) - sum_j my_j*log2(my_j)
// Round 4: revert main to round-2 config (1024thr/148blk/unroll-4, best so
// far); fuse the marginal finalization into the main kernel via a
// last-block-done ticket (fp32 __log2f + fp64 accumulation), killing the
// 13-26us single-block fp64 final kernel and one launch.

#define NROWS 8192
#define MCOLS 8192
#define NTHREADS 1024
#define NBLOCKS 148

__device__ float        g_rowsum[NROWS];
__device__ float        g_colsum[MCOLS];
__device__ double       g_clogc;
__device__ unsigned int g_done;

__global__ void mi_zero_kernel() {
    int t = blockIdx.x * blockDim.x + threadIdx.x;
    int stride = gridDim.x * blockDim.x;
    for (int i = t; i < NROWS; i += stride) g_rowsum[i] = 0.0f;
    for (int i = t; i < MCOLS; i += stride) g_colsum[i] = 0.0f;
    if (t == 0) { g_clogc = 0.0; g_done = 0u; }
}

// c*log2(c) masked at c>0, branchless, exact at c==0 (0 * finite = 0).
__device__ __forceinline__ void clog2c(float v, float& acc) {
    acc = __fmaf_rn(v, __log2f(fmaxf(v, 1e-30f)), acc);
}
__device__ __forceinline__ void clog4(const float4& v, float& acc) {
    clog2c(v.x, acc); clog2c(v.y, acc); clog2c(v.z, acc); clog2c(v.w, acc);
}
__device__ __forceinline__ float sum4(const float4& v) {
    return (v.x + v.y) + (v.z + v.w);
}

__global__ __launch_bounds__(NTHREADS, 1)
void mi_main_kernel(const float* __restrict__ C, float* __restrict__ out) {
    const int t = threadIdx.x;

    // Thread-fixed columns: {4t..4t+3} and {4096+4t..4096+4t+3}.
    float ac0 = 0.f, ac1 = 0.f, ac2 = 0.f, ac3 = 0.f;
    float ac4 = 0.f, ac5 = 0.f, ac6 = 0.f, ac7 = 0.f;
    float cl0 = 0.f, cl1 = 0.f;

    const int base = blockIdx.x;
    const int cnt = (NROWS - 1 - base) / NBLOCKS + 1;

    int k = 0;
    for (; k + 4 <= cnt; k += 4) {
        const int r0 = base + (k + 0) * NBLOCKS;
        const int r1 = base + (k + 1) * NBLOCKS;
        const int r2 = base + (k + 2) * NBLOCKS;
        const int r3 = base + (k + 3) * NBLOCKS;
        const float4* p0 = reinterpret_cast<const float4*>(C + (size_t)r0 * MCOLS);
        const float4* p1 = reinterpret_cast<const float4*>(C + (size_t)r1 * MCOLS);
        const float4* p2 = reinterpret_cast<const float4*>(C + (size_t)r2 * MCOLS);
        const float4* p3 = reinterpret_cast<const float4*>(C + (size_t)r3 * MCOLS);

        // 8 independent LDG.128 in flight per thread.
        float4 a0 = p0[t], a1 = p0[t + NTHREADS];
        float4 b0 = p1[t], b1 = p1[t + NTHREADS];
        float4 c0 = p2[t], c1 = p2[t + NTHREADS];
        float4 d0 = p3[t], d1 = p3[t + NTHREADS];

        float rs0 = sum4(a0) + sum4(a1);
        float rs1 = sum4(b0) + sum4(b1);
        float rs2 = sum4(c0) + sum4(c1);
        float rs3 = sum4(d0) + sum4(d1);

        ac0 += (a0.x + b0.x) + (c0.x + d0.x);
        ac1 += (a0.y + b0.y) + (c0.y + d0.y);
        ac2 += (a0.z + b0.z) + (c0.z + d0.z);
        ac3 += (a0.w + b0.w) + (c0.w + d0.w);
        ac4 += (a1.x + b1.x) + (c1.x + d1.x);
        ac5 += (a1.y + b1.y) + (c1.y + d1.y);
        ac6 += (a1.z + b1.z) + (c1.z + d1.z);
        ac7 += (a1.w + b1.w) + (c1.w + d1.w);

        clog4(a0, cl0); clog4(a1, cl1);
        clog4(b0, cl0); clog4(b1, cl1);
        clog4(c0, cl0); clog4(c1, cl1);
        clog4(d0, cl0); clog4(d1, cl1);

        #pragma unroll
        for (int off = 16; off > 0; off >>= 1) {
            rs0 += __shfl_down_sync(0xffffffffu, rs0, off);
            rs1 += __shfl_down_sync(0xffffffffu, rs1, off);
            rs2 += __shfl_down_sync(0xffffffffu, rs2, off);
            rs3 += __shfl_down_sync(0xffffffffu, rs3, off);
        }
        if ((t & 31) == 0) {
            atomicAdd(&g_rowsum[r0], rs0);
            atomicAdd(&g_rowsum[r1], rs1);
            atomicAdd(&g_rowsum[r2], rs2);
            atomicAdd(&g_rowsum[r3], rs3);
        }
    }

    for (; k < cnt; ++k) {
        const int r = base + k * NBLOCKS;
        const float4* p = reinterpret_cast<const float4*>(C + (size_t)r * MCOLS);
        float4 v0 = p[t], v1 = p[t + NTHREADS];

        float rs = sum4(v0) + sum4(v1);

        ac0 += v0.x; ac1 += v0.y; ac2 += v0.z; ac3 += v0.w;
        ac4 += v1.x; ac5 += v1.y; ac6 += v1.z; ac7 += v1.w;

        clog4(v0, cl0); clog4(v1, cl1);

        #pragma unroll
        for (int off = 16; off > 0; off >>= 1)
            rs += __shfl_down_sync(0xffffffffu, rs, off);
        if ((t & 31) == 0)
            atomicAdd(&g_rowsum[r], rs);
    }

    // Flush column accumulators.
    int cA = 4 * t;
    atomicAdd(&g_colsum[cA + 0], ac0);
    atomicAdd(&g_colsum[cA + 1], ac1);
    atomicAdd(&g_colsum[cA + 2], ac2);
    atomicAdd(&g_colsum[cA + 3], ac3);
    int cB = 4 * NTHREADS + 4 * t;
    atomicAdd(&g_colsum[cB + 0], ac4);
    atomicAdd(&g_colsum[cB + 1], ac5);
    atomicAdd(&g_colsum[cB + 2], ac6);
    atomicAdd(&g_colsum[cB + 3], ac7);

    // clogc cross-thread reduction in double.
    double d = (double)(cl0 + cl1);
    #pragma unroll
    for (int off = 16; off > 0; off >>= 1)
        d += __shfl_down_sync(0xffffffffu, d, off);
    if ((t & 31) == 0)
        atomicAdd(&g_clogc, d);

    // ---- fused finalization: last block to finish does the marginal sums ----
    __shared__ unsigned int s_islast;
    __threadfence();  // make this block's atomics visible device-wide
    __syncthreads();  // all warps' atomics issued before the ticket
    if (t == 0)
        s_islast = (atomicAdd(&g_done, 1u) == (unsigned)(gridDim.x - 1));
    __syncthreads();
    if (!s_islast) return;

    // All other blocks have fenced + ticketed: g_rowsum/g_colsum/g_clogc final.
    double local = 0.0;
    for (int i = t; i < NROWS; i += NTHREADS) {
        float mx = g_rowsum[i];
        if (mx > 0.f) local += (double)mx * (double)__log2f(mx);
    }
    for (int j = t; j < MCOLS; j += NTHREADS) {
        float my = g_colsum[j];
        if (my > 0.f) local += (double)my * (double)__log2f(my);
    }

    __shared__ double sh[NTHREADS / 32];
    #pragma unroll
    for (int off = 16; off > 0; off >>= 1)
        local += __shfl_down_sync(0xffffffffu, local, off);
    if ((t & 31) == 0) sh[t >> 5] = local;
    __syncthreads();
    if (t < 32) {
        double v = (t < (NTHREADS / 32)) ? sh[t] : 0.0;
        #pragma unroll
        for (int off = 16; off > 0; off >>= 1)
            v += __shfl_down_sync(0xffffffffu, v, off);
        if (t == 0)
            out[0] = (float)(g_clogc - v);
    }
}

extern "C" void kernel_launch(void* const* d_in, const int* in_sizes, int n_in,
                              void* d_out, int out_size) {
    const float* C = (const float*)d_in[0];
    float* out = (float*)d_out;

    mi_zero_kernel<<<16, 1024>>>();
    mi_main_kernel<<<NBLOCKS, NTHREADS>>>(C, out);
}